// round 15
// baseline (speedup 1.0000x reference)
#include <cuda_runtime.h>
#include <cuda_fp16.h>
#include <math.h>

#define Bn 16
#define Sn 512
#define Vn 4096
#define CHUNKS (Vn / 128)          // 32 k-chunks of 128 bytes
#define SINK_CTAS 128              // persistent Sinkhorn grid (< 148 SMs)

// ---------------- scratch (device globals; no allocation allowed) ----------------
__device__ __align__(256) unsigned char g_qs[Bn * Sn * Vn];  // q8 softmax(y_s/T)
__device__ __align__(256) unsigned char g_qt[Bn * Sn * Vn];  // q8 softmax(y_t/T)
__device__ __align__(256) __half g_Wh[Bn * Sn * Sn];         // L1 cost, fp16
__device__ __align__(256) __half g_Kh[Bn * Sn * Sn];         // (exp(-10W)+1e-8)*8192
__device__ __align__(256) __half g_KTh[Bn * Sn * Sn];        // transpose of g_Kh
__device__ __align__(256) float g_r[Bn * Sn];                // Sinkhorn row scalings
__device__ __align__(256) float g_c[Bn * Sn];                // Sinkhorn col scalings
__device__ __align__(256) float g_part[256];                 // loss partials
__device__ int g_bcnt = 0;                                   // barrier counter
__device__ int g_bsense = 0;                                 // barrier sense (even flips/launch)

// ---------------- cp.async helpers ----------------
__device__ __forceinline__ void cp16(unsigned dst, const void* src) {
    asm volatile("cp.async.ca.shared.global [%0], [%1], 16;" :: "r"(dst), "l"(src));
}
#define CP_COMMIT() asm volatile("cp.async.commit_group;")
#define CP_WAIT1()  asm volatile("cp.async.wait_group 1;")
#define CP_WAIT0()  asm volatile("cp.async.wait_group 0;")

// ---------------- reductions ----------------
__device__ __forceinline__ float warpSum(float v) {
#pragma unroll
    for (int o = 16; o; o >>= 1) v += __shfl_xor_sync(0xffffffffu, v, o);
    return v;
}
__device__ __forceinline__ float warpMax(float v) {
#pragma unroll
    for (int o = 16; o; o >>= 1) v = fmaxf(v, __shfl_xor_sync(0xffffffffu, v, o));
    return v;
}
__device__ __forceinline__ float blockSum(float v, float* sh) {
    int t = threadIdx.x;
    __syncthreads();
    v = warpSum(v);
    if ((t & 31) == 0) sh[t >> 5] = v;
    __syncthreads();
    float r = (t < (int)(blockDim.x >> 5)) ? sh[t] : 0.0f;
    if (t < 32) {
        r = warpSum(r);
        if (t == 0) sh[0] = r;
    }
    __syncthreads();
    return sh[0];
}
__device__ __forceinline__ float blockMax(float v, float* sh) {
    int t = threadIdx.x;
    __syncthreads();
    v = warpMax(v);
    if ((t & 31) == 0) sh[t >> 5] = v;
    __syncthreads();
    float r = (t < (int)(blockDim.x >> 5)) ? sh[t] : -INFINITY;
    if (t < 32) {
        r = warpMax(r);
        if (t == 0) sh[0] = r;
    }
    __syncthreads();
    return sh[0];
}

// ---------------- device-wide sense-reversing barrier (all SINK_CTAS resident) ---
__device__ __forceinline__ void gridBar(int& sense) {
    __syncthreads();
    if (threadIdx.x == 0) {
        sense ^= 1;
        __threadfence();
        int v = atomicAdd(&g_bcnt, 1);
        if (v == SINK_CTAS - 1) {
            atomicExch(&g_bcnt, 0);
            __threadfence();
            atomicExch(&g_bsense, sense);
        } else {
            while (atomicAdd(&g_bsense, 0) != sense) { __nanosleep(32); }
        }
        __threadfence();
    }
    __syncthreads();
}

// ---------------- softmax over V (T=2) -> uint8 quantized (scale 2^17) -----------
__global__ void __launch_bounds__(256) softmax_k(const float* __restrict__ ys,
                                                 const float* __restrict__ yt) {
    __shared__ float sh[32];
    int row = blockIdx.x;                       // 0 .. 2*B*S-1
    const float4* src;
    uint4* dst;
    if (row < Bn * Sn) {
        src = (const float4*)ys + (size_t)row * (Vn / 4);
        dst = (uint4*)g_qs + (size_t)row * (Vn / 16);
    } else {
        int r2 = row - Bn * Sn;
        src = (const float4*)yt + (size_t)r2 * (Vn / 4);
        dst = (uint4*)g_qt + (size_t)r2 * (Vn / 16);
    }
    int t = threadIdx.x;                        // thread owns v in [16t, 16t+16)
    float4 x[4];
    float m = -INFINITY;
#pragma unroll
    for (int k = 0; k < 4; k++) {
        float4 v = src[4 * t + k];
        v.x *= 0.5f; v.y *= 0.5f; v.z *= 0.5f; v.w *= 0.5f;   // y / T, T = 2
        x[k] = v;
        m = fmaxf(m, fmaxf(fmaxf(v.x, v.y), fmaxf(v.z, v.w)));
    }
    m = blockMax(m, sh);
    float s = 0.0f;
#pragma unroll
    for (int k = 0; k < 4; k++) {
        x[k].x = __expf(x[k].x - m);
        x[k].y = __expf(x[k].y - m);
        x[k].z = __expf(x[k].z - m);
        x[k].w = __expf(x[k].w - m);
        s += (x[k].x + x[k].y) + (x[k].z + x[k].w);
    }
    s = blockSum(s, sh);
    float f = 131072.0f / s;                    // p * 2^17
    unsigned q[16];
#pragma unroll
    for (int k = 0; k < 4; k++) {
        q[4 * k + 0] = __float2uint_rn(fminf(x[k].x * f, 255.0f));
        q[4 * k + 1] = __float2uint_rn(fminf(x[k].y * f, 255.0f));
        q[4 * k + 2] = __float2uint_rn(fminf(x[k].z * f, 255.0f));
        q[4 * k + 3] = __float2uint_rn(fminf(x[k].w * f, 255.0f));
    }
    uint4 u;
    u.x = q[0]  | (q[1] << 8)  | (q[2] << 16)  | (q[3] << 24);
    u.y = q[4]  | (q[5] << 8)  | (q[6] << 16)  | (q[7] << 24);
    u.z = q[8]  | (q[9] << 8)  | (q[10] << 16) | (q[11] << 24);
    u.w = q[12] | (q[13] << 8) | (q[14] << 16) | (q[15] << 24);
    dst[t] = u;
}

// ---------------- L1 cdist via integer SAD; emits W, K', K'^T (all fp16) ----------
// CTA 128x128 tile, 256 threads (16x16), 8x8 outputs/thread.
// cp.async triple-buffered smem (3 stages x (A,B) x 16KB = 96KB), 1 sync/chunk.
// launch_bounds(256,2): cap regs at 128 so 2 CTAs/SM stay resident (192KB smem OK).
extern __shared__ uint4 smem_dyn[];
__global__ void __launch_bounds__(256, 2) minsum_k() {
    int b  = blockIdx.z;
    int i0 = blockIdx.x * 128;
    int j0 = blockIdx.y * 128;
    int tid = threadIdx.x;
    int tx = tid & 15, ty = tid >> 4;

    unsigned sbase = (unsigned)__cvta_generic_to_shared(smem_dyn);

    // loader: word w = tid&7, base row lr = tid>>3 (32 rows/pass, 4 passes)
    int w = tid & 7, lr = tid >> 3;
    const char* Ag = (const char*)g_qs + (size_t)(b * Sn + i0) * Vn;
    const char* Bg = (const char*)g_qt + (size_t)(b * Sn + j0) * Vn;

    auto issue = [&](int c, int st) {
        unsigned sa = sbase + (unsigned)(st * 2048) * 16;
        unsigned sb = sa + 1024 * 16;
        const char* ag = Ag + c * 128 + w * 16;
        const char* bg = Bg + c * 128 + w * 16;
#pragma unroll
        for (int m = 0; m < 4; m++) {
            int rr = lr + 32 * m;
            int col = w ^ ((rr ^ (rr >> 3)) & 7);
            unsigned so = (unsigned)(rr * 8 + col) * 16;
            cp16(sa + so, ag + (size_t)rr * Vn);
            cp16(sb + so, bg + (size_t)rr * Vn);
        }
        CP_COMMIT();
    };

    unsigned acc[8][8];
#pragma unroll
    for (int ii = 0; ii < 8; ii++)
#pragma unroll
        for (int jj = 0; jj < 8; jj++) acc[ii][jj] = 0u;

    issue(0, 0);
    issue(1, 1);

    for (int c = 0; c < CHUNKS; ++c) {
        if (c + 1 < CHUNKS) CP_WAIT1(); else CP_WAIT0();
        __syncthreads();                 // chunk c resident; all done reading c-1
        if (c + 2 < CHUNKS) issue(c + 2, (c + 2) % 3);

        const uint4* sa = smem_dyn + (c % 3) * 2048;
        const uint4* sb = sa + 1024;
#pragma unroll
        for (int gg = 0; gg < 8; ++gg) {        // 16 v per sub-chunk
            uint4 af[8], bf[8];
#pragma unroll
            for (int jj = 0; jj < 8; jj++)
                bf[jj] = sb[(8 * tx + jj) * 8 + (gg ^ ((jj ^ tx) & 7))];
#pragma unroll
            for (int ii = 0; ii < 8; ii++)
                af[ii] = sa[(8 * ty + ii) * 8 + (gg ^ ((ii ^ ty) & 7))];
#pragma unroll
            for (int ii = 0; ii < 8; ii++) {
#pragma unroll
                for (int jj = 0; jj < 8; jj++) {
                    acc[ii][jj] += __vsadu4(af[ii].x, bf[jj].x);
                    acc[ii][jj] += __vsadu4(af[ii].y, bf[jj].y);
                    acc[ii][jj] += __vsadu4(af[ii].z, bf[jj].z);
                    acc[ii][jj] += __vsadu4(af[ii].w, bf[jj].w);
                }
            }
        }
        __syncthreads();                 // done reading stage c%3 (reused at c+3)
    }

    // epilogue: W = acc/2^17; K' = (exp(-10*min(W,10)) + 1e-8) * 8192
    __half kt[8][8];                     // [jj][ii]
#pragma unroll
    for (int ii = 0; ii < 8; ii++) {
        int i = i0 + 8 * ty + ii;
        __align__(16) __half wv[8];
        __align__(16) __half kv[8];
#pragma unroll
        for (int jj = 0; jj < 8; jj++) {
            float W = (float)acc[ii][jj] * (1.0f / 131072.0f);
            float K = (__expf(-10.0f * fminf(W, 10.0f)) + 1e-8f) * 8192.0f;
            wv[jj] = __float2half_rn(W);
            kv[jj] = __float2half_rn(K);
            kt[jj][ii] = kv[jj];
        }
        size_t off = ((size_t)(b * Sn + i) * Sn + j0 + 8 * tx) >> 3;  // uint4 units
        ((uint4*)g_Wh)[off] = *(const uint4*)wv;
        ((uint4*)g_Kh)[off] = *(const uint4*)kv;
    }
#pragma unroll
    for (int jj = 0; jj < 8; jj++) {
        int j = j0 + 8 * tx + jj;
        size_t off = ((size_t)(b * Sn + j) * Sn + i0 + 8 * ty) >> 3;
        ((uint4*)g_KTh)[off] = *(const uint4*)kt[jj];
    }
}

// ---------------- one Sinkhorn half-step for 4 rows (warp-collective) ------------
__device__ __forceinline__ void sink4(const __half* __restrict__ M,
                                      const float* __restrict__ vin,
                                      float* __restrict__ vout,
                                      int b, int row0, int lane,
                                      bool ones, bool fresh) {
    float4 c0, c1, c2, c3;
    if (!ones) {
        const float4* vp = (const float4*)(vin + b * Sn) + lane * 4;
        c0 = vp[0]; c1 = vp[1]; c2 = vp[2]; c3 = vp[3];
    }
    const uint4* Mb = (const uint4*)(M + ((size_t)(b * Sn + row0)) * Sn) + lane * 2;
    uint4 u[8];
#pragma unroll
    for (int rr = 0; rr < 4; rr++) {
        u[2 * rr]     = Mb[rr * (Sn / 8)];
        u[2 * rr + 1] = Mb[rr * (Sn / 8) + 1];
    }
#pragma unroll
    for (int rr = 0; rr < 4; rr++) {
        const __half2* h0 = (const __half2*)&u[2 * rr];
        const __half2* h1 = (const __half2*)&u[2 * rr + 1];
        float s = 0.0f;
        if (ones) {
#pragma unroll
            for (int k = 0; k < 4; k++) {
                float2 a = __half22float2(h0[k]);
                float2 bb = __half22float2(h1[k]);
                s += (a.x + a.y) + (bb.x + bb.y);
            }
        } else {
            float2 a;
            a = __half22float2(h0[0]); s += a.x * c0.x + a.y * c0.y;
            a = __half22float2(h0[1]); s += a.x * c0.z + a.y * c0.w;
            a = __half22float2(h0[2]); s += a.x * c1.x + a.y * c1.y;
            a = __half22float2(h0[3]); s += a.x * c1.z + a.y * c1.w;
            a = __half22float2(h1[0]); s += a.x * c2.x + a.y * c2.y;
            a = __half22float2(h1[1]); s += a.x * c2.z + a.y * c2.w;
            a = __half22float2(h1[2]); s += a.x * c3.x + a.y * c3.y;
            a = __half22float2(h1[3]); s += a.x * c3.z + a.y * c3.w;
        }
        s = warpSum(s);
        if (lane == 0) {
            int idx = b * Sn + row0 + rr;
            if (fresh) {
                vout[idx] = 1.0f / fmaxf(s, 1e-8f);
            } else {
                float vo = vout[idx];
                vout[idx] = vo / fmaxf(vo * s, 1e-8f);
            }
        }
    }
}

// ---------------- persistent Sinkhorn: all 10 iterations, 20 grid barriers -------
// 128 CTAs (8 per batch) x 256 threads; each warp owns 8 rows (2 passes of 4).
// 20 barriers per launch = even # sense flips -> barrier state self-restores
// across graph replays. No smem, low regs -> guaranteed co-residency.
__global__ void __launch_bounds__(256) sinkhorn_k() {
    int cta = blockIdx.x;                 // 0..127
    int b = cta >> 3, sub = cta & 7;
    int wid = threadIdx.x >> 5, lane = threadIdx.x & 31;
    int row0 = sub * 64 + wid * 8;        // this warp: rows [row0, row0+8)
    int sense = 0;
    for (int it = 0; it < 10; ++it) {
        bool f = (it == 0);
        sink4(g_Kh, g_c, g_r, b, row0,     lane, f, f);   // row step
        sink4(g_Kh, g_c, g_r, b, row0 + 4, lane, f, f);
        gridBar(sense);
        sink4(g_KTh, g_r, g_c, b, row0,     lane, false, f);  // col step
        sink4(g_KTh, g_r, g_c, b, row0 + 4, lane, false, f);
        gridBar(sense);
    }
}

// ---------------- loss = sum_b sum_ij r_i c_j K'_ij W_ij (K' scale cancels) ------
__global__ void __launch_bounds__(256) losspart_k() {
    __shared__ float sh[32];
    int bx = blockIdx.x;                        // 16 batches x 16 row-tiles of 32
    int b = bx >> 4, i0 = (bx & 15) * 32;
    int t = threadIdx.x;
    const uint4* K4 = (const uint4*)g_Kh + (size_t)(b * Sn + i0) * (Sn / 8);
    const uint4* W4 = (const uint4*)g_Wh + (size_t)(b * Sn + i0) * (Sn / 8);
    float p = 0.0f;
#pragma unroll
    for (int m = 0; m < 8; m++) {
        int o = t + 256 * m;                    // 32 rows x 64 uint4
        int i = o >> 6, j8 = o & 63;
        uint4 ku = K4[o], wu = W4[o];
        const __half2* kh = (const __half2*)&ku;
        const __half2* wh = (const __half2*)&wu;
        const float4* cp = (const float4*)(g_c + b * Sn + j8 * 8);
        float4 c0 = cp[0], c1 = cp[1];
        float ri = g_r[b * Sn + i0 + i];
        float2 k0, w0;
        float s = 0.0f;
        k0 = __half22float2(kh[0]); w0 = __half22float2(wh[0]);
        s += c0.x * k0.x * w0.x + c0.y * k0.y * w0.y;
        k0 = __half22float2(kh[1]); w0 = __half22float2(wh[1]);
        s += c0.z * k0.x * w0.x + c0.w * k0.y * w0.y;
        k0 = __half22float2(kh[2]); w0 = __half22float2(wh[2]);
        s += c1.x * k0.x * w0.x + c1.y * k0.y * w0.y;
        k0 = __half22float2(kh[3]); w0 = __half22float2(wh[3]);
        s += c1.z * k0.x * w0.x + c1.w * k0.y * w0.y;
        p += ri * s;
    }
    p = blockSum(p, sh);
    if (t == 0) g_part[bx] = p;
}

__global__ void __launch_bounds__(256) lossfin_k(float* __restrict__ out) {
    __shared__ float sh[32];
    int t = threadIdx.x;
    float v = g_part[t];                        // exactly 256 partials
    v = blockSum(v, sh);
    if (t == 0) out[0] = v * (0.001f / 16.0f);  // mean over B of 0.001 * loss_b
}

// ---------------- launch --------------------------------------------------------
extern "C" void kernel_launch(void* const* d_in, const int* in_sizes, int n_in,
                              void* d_out, int out_size) {
    const float* ys = (const float*)d_in[0];
    const float* yt = (const float*)d_in[1];
    (void)in_sizes; (void)n_in; (void)out_size;

    // idempotent; called every time (no static guards allowed)
    cudaFuncSetAttribute(minsum_k, cudaFuncAttributeMaxDynamicSharedMemorySize,
                         98304);

    softmax_k<<<2 * Bn * Sn, 256>>>(ys, yt);

    dim3 grid(Sn / 128, Sn / 128, Bn);          // 4 x 4 x 16 = 256 CTAs
    minsum_k<<<grid, 256, 98304>>>();

    sinkhorn_k<<<SINK_CTAS, 256>>>();           // all 10 iterations, 1 launch

    losspart_k<<<Bn * 16, 256>>>();
    lossfin_k<<<1, 256>>>((float*)d_out);
}

// round 16
// speedup vs baseline: 1.0248x; 1.0248x over previous
#include <cuda_runtime.h>
#include <cuda_fp16.h>
#include <math.h>

#define Bn 16
#define Sn 512
#define Vn 4096
#define CHUNKS (Vn / 128)          // 32 k-chunks of 128 bytes
#define SINK_CTAS 128              // persistent Sinkhorn grid (< 148 SMs)

// ---------------- scratch (device globals; no allocation allowed) ----------------
__device__ __align__(256) unsigned char g_qs[Bn * Sn * Vn];  // q8 softmax(y_s/T)
__device__ __align__(256) unsigned char g_qt[Bn * Sn * Vn];  // q8 softmax(y_t/T)
__device__ __align__(256) __half g_Wh[Bn * Sn * Sn];         // L1 cost, fp16
__device__ __align__(256) __half g_Kh[Bn * Sn * Sn];         // (exp(-10W)+1e-8)*8192
__device__ __align__(256) __half g_KTh[Bn * Sn * Sn];        // transpose of g_Kh
__device__ __align__(256) float g_r[Bn * Sn];                // Sinkhorn row scalings
__device__ __align__(256) float g_c[Bn * Sn];                // Sinkhorn col scalings
__device__ __align__(256) float g_part[1024];                // loss partials
__device__ int g_bcnt = 0;                                   // barrier counter
__device__ int g_bsense = 0;                                 // barrier sense (even flips/launch)

// ---------------- cp.async helpers ----------------
__device__ __forceinline__ void cp16(unsigned dst, const void* src) {
    asm volatile("cp.async.ca.shared.global [%0], [%1], 16;" :: "r"(dst), "l"(src));
}
#define CP_COMMIT() asm volatile("cp.async.commit_group;")
#define CP_WAIT1()  asm volatile("cp.async.wait_group 1;")
#define CP_WAIT0()  asm volatile("cp.async.wait_group 0;")

// ---------------- reductions ----------------
__device__ __forceinline__ float warpSum(float v) {
#pragma unroll
    for (int o = 16; o; o >>= 1) v += __shfl_xor_sync(0xffffffffu, v, o);
    return v;
}
__device__ __forceinline__ float warpMax(float v) {
#pragma unroll
    for (int o = 16; o; o >>= 1) v = fmaxf(v, __shfl_xor_sync(0xffffffffu, v, o));
    return v;
}
__device__ __forceinline__ float blockSum(float v, float* sh) {
    int t = threadIdx.x;
    __syncthreads();
    v = warpSum(v);
    if ((t & 31) == 0) sh[t >> 5] = v;
    __syncthreads();
    float r = (t < (int)(blockDim.x >> 5)) ? sh[t] : 0.0f;
    if (t < 32) {
        r = warpSum(r);
        if (t == 0) sh[0] = r;
    }
    __syncthreads();
    return sh[0];
}
__device__ __forceinline__ float blockMax(float v, float* sh) {
    int t = threadIdx.x;
    __syncthreads();
    v = warpMax(v);
    if ((t & 31) == 0) sh[t >> 5] = v;
    __syncthreads();
    float r = (t < (int)(blockDim.x >> 5)) ? sh[t] : -INFINITY;
    if (t < 32) {
        r = warpMax(r);
        if (t == 0) sh[0] = r;
    }
    __syncthreads();
    return sh[0];
}

// ---------------- device-wide sense-reversing barrier (all SINK_CTAS resident) ---
__device__ __forceinline__ void gridBar(int& sense) {
    __syncthreads();
    if (threadIdx.x == 0) {
        sense ^= 1;
        __threadfence();
        int v = atomicAdd(&g_bcnt, 1);
        if (v == SINK_CTAS - 1) {
            atomicExch(&g_bcnt, 0);
            __threadfence();
            atomicExch(&g_bsense, sense);
        } else {
            while (atomicAdd(&g_bsense, 0) != sense) { __nanosleep(32); }
        }
        __threadfence();
    }
    __syncthreads();
}

// ---------------- softmax over V (T=2) -> uint8 quantized (scale 2^17) -----------
__global__ void __launch_bounds__(256) softmax_k(const float* __restrict__ ys,
                                                 const float* __restrict__ yt) {
    __shared__ float sh[32];
    int row = blockIdx.x;                       // 0 .. 2*B*S-1
    const float4* src;
    uint4* dst;
    if (row < Bn * Sn) {
        src = (const float4*)ys + (size_t)row * (Vn / 4);
        dst = (uint4*)g_qs + (size_t)row * (Vn / 16);
    } else {
        int r2 = row - Bn * Sn;
        src = (const float4*)yt + (size_t)r2 * (Vn / 4);
        dst = (uint4*)g_qt + (size_t)r2 * (Vn / 16);
    }
    int t = threadIdx.x;                        // thread owns v in [16t, 16t+16)
    float4 x[4];
    float m = -INFINITY;
#pragma unroll
    for (int k = 0; k < 4; k++) {
        float4 v = src[4 * t + k];
        v.x *= 0.5f; v.y *= 0.5f; v.z *= 0.5f; v.w *= 0.5f;   // y / T, T = 2
        x[k] = v;
        m = fmaxf(m, fmaxf(fmaxf(v.x, v.y), fmaxf(v.z, v.w)));
    }
    m = blockMax(m, sh);
    float s = 0.0f;
#pragma unroll
    for (int k = 0; k < 4; k++) {
        x[k].x = __expf(x[k].x - m);
        x[k].y = __expf(x[k].y - m);
        x[k].z = __expf(x[k].z - m);
        x[k].w = __expf(x[k].w - m);
        s += (x[k].x + x[k].y) + (x[k].z + x[k].w);
    }
    s = blockSum(s, sh);
    float f = 131072.0f / s;                    // p * 2^17
    unsigned q[16];
#pragma unroll
    for (int k = 0; k < 4; k++) {
        q[4 * k + 0] = __float2uint_rn(fminf(x[k].x * f, 255.0f));
        q[4 * k + 1] = __float2uint_rn(fminf(x[k].y * f, 255.0f));
        q[4 * k + 2] = __float2uint_rn(fminf(x[k].z * f, 255.0f));
        q[4 * k + 3] = __float2uint_rn(fminf(x[k].w * f, 255.0f));
    }
    uint4 u;
    u.x = q[0]  | (q[1] << 8)  | (q[2] << 16)  | (q[3] << 24);
    u.y = q[4]  | (q[5] << 8)  | (q[6] << 16)  | (q[7] << 24);
    u.z = q[8]  | (q[9] << 8)  | (q[10] << 16) | (q[11] << 24);
    u.w = q[12] | (q[13] << 8) | (q[14] << 16) | (q[15] << 24);
    dst[t] = u;
}

// ---------------- L1 cdist via integer SAD; emits W, K', K'^T (all fp16) ----------
// CTA 128x128 tile, 256 threads (16x16), 8x8 outputs/thread.
// cp.async triple-buffered smem (3 stages x (A,B) x 16KB = 96KB), 1 sync/chunk.
// (256,1): full register budget — (256,2) in R14 forced acc spills, +190us. Reverted.
extern __shared__ uint4 smem_dyn[];
__global__ void __launch_bounds__(256, 1) minsum_k() {
    int b  = blockIdx.z;
    int i0 = blockIdx.x * 128;
    int j0 = blockIdx.y * 128;
    int tid = threadIdx.x;
    int tx = tid & 15, ty = tid >> 4;

    unsigned sbase = (unsigned)__cvta_generic_to_shared(smem_dyn);

    // loader: word w = tid&7, base row lr = tid>>3 (32 rows/pass, 4 passes)
    int w = tid & 7, lr = tid >> 3;
    const char* Ag = (const char*)g_qs + (size_t)(b * Sn + i0) * Vn;
    const char* Bg = (const char*)g_qt + (size_t)(b * Sn + j0) * Vn;

    auto issue = [&](int c, int st) {
        unsigned sa = sbase + (unsigned)(st * 2048) * 16;
        unsigned sb = sa + 1024 * 16;
        const char* ag = Ag + c * 128 + w * 16;
        const char* bg = Bg + c * 128 + w * 16;
#pragma unroll
        for (int m = 0; m < 4; m++) {
            int rr = lr + 32 * m;
            int col = w ^ ((rr ^ (rr >> 3)) & 7);
            unsigned so = (unsigned)(rr * 8 + col) * 16;
            cp16(sa + so, ag + (size_t)rr * Vn);
            cp16(sb + so, bg + (size_t)rr * Vn);
        }
        CP_COMMIT();
    };

    unsigned acc[8][8];
#pragma unroll
    for (int ii = 0; ii < 8; ii++)
#pragma unroll
        for (int jj = 0; jj < 8; jj++) acc[ii][jj] = 0u;

    issue(0, 0);
    issue(1, 1);

    for (int c = 0; c < CHUNKS; ++c) {
        if (c + 1 < CHUNKS) CP_WAIT1(); else CP_WAIT0();
        __syncthreads();                 // chunk c resident; all done reading c-1
        if (c + 2 < CHUNKS) issue(c + 2, (c + 2) % 3);

        const uint4* sa = smem_dyn + (c % 3) * 2048;
        const uint4* sb = sa + 1024;
#pragma unroll
        for (int gg = 0; gg < 8; ++gg) {        // 16 v per sub-chunk
            uint4 af[8], bf[8];
#pragma unroll
            for (int jj = 0; jj < 8; jj++)
                bf[jj] = sb[(8 * tx + jj) * 8 + (gg ^ ((jj ^ tx) & 7))];
#pragma unroll
            for (int ii = 0; ii < 8; ii++)
                af[ii] = sa[(8 * ty + ii) * 8 + (gg ^ ((ii ^ ty) & 7))];
#pragma unroll
            for (int ii = 0; ii < 8; ii++) {
#pragma unroll
                for (int jj = 0; jj < 8; jj++) {
                    acc[ii][jj] += __vsadu4(af[ii].x, bf[jj].x);
                    acc[ii][jj] += __vsadu4(af[ii].y, bf[jj].y);
                    acc[ii][jj] += __vsadu4(af[ii].z, bf[jj].z);
                    acc[ii][jj] += __vsadu4(af[ii].w, bf[jj].w);
                }
            }
        }
        __syncthreads();                 // done reading stage c%3 (reused at c+3)
    }

    // epilogue: W = acc/2^17; K' = (exp(-10*min(W,10)) + 1e-8) * 8192
    __half kt[8][8];                     // [jj][ii]
#pragma unroll
    for (int ii = 0; ii < 8; ii++) {
        int i = i0 + 8 * ty + ii;
        __align__(16) __half wv[8];
        __align__(16) __half kv[8];
#pragma unroll
        for (int jj = 0; jj < 8; jj++) {
            float W = (float)acc[ii][jj] * (1.0f / 131072.0f);
            float K = (__expf(-10.0f * fminf(W, 10.0f)) + 1e-8f) * 8192.0f;
            wv[jj] = __float2half_rn(W);
            kv[jj] = __float2half_rn(K);
            kt[jj][ii] = kv[jj];
        }
        size_t off = ((size_t)(b * Sn + i) * Sn + j0 + 8 * tx) >> 3;  // uint4 units
        ((uint4*)g_Wh)[off] = *(const uint4*)wv;
        ((uint4*)g_Kh)[off] = *(const uint4*)kv;
    }
#pragma unroll
    for (int jj = 0; jj < 8; jj++) {
        int j = j0 + 8 * tx + jj;
        size_t off = ((size_t)(b * Sn + j) * Sn + i0 + 8 * ty) >> 3;
        ((uint4*)g_KTh)[off] = *(const uint4*)kt[jj];
    }
}

// ---------------- one Sinkhorn half-step for 4 rows (warp-collective) ------------
__device__ __forceinline__ void sink4(const __half* __restrict__ M,
                                      const float* __restrict__ vin,
                                      float* __restrict__ vout,
                                      int b, int row0, int lane,
                                      bool ones, bool fresh) {
    float4 c0, c1, c2, c3;
    if (!ones) {
        const float4* vp = (const float4*)(vin + b * Sn) + lane * 4;
        c0 = vp[0]; c1 = vp[1]; c2 = vp[2]; c3 = vp[3];
    }
    const uint4* Mb = (const uint4*)(M + ((size_t)(b * Sn + row0)) * Sn) + lane * 2;
    uint4 u[8];
#pragma unroll
    for (int rr = 0; rr < 4; rr++) {
        u[2 * rr]     = Mb[rr * (Sn / 8)];
        u[2 * rr + 1] = Mb[rr * (Sn / 8) + 1];
    }
#pragma unroll
    for (int rr = 0; rr < 4; rr++) {
        const __half2* h0 = (const __half2*)&u[2 * rr];
        const __half2* h1 = (const __half2*)&u[2 * rr + 1];
        float s = 0.0f;
        if (ones) {
#pragma unroll
            for (int k = 0; k < 4; k++) {
                float2 a = __half22float2(h0[k]);
                float2 bb = __half22float2(h1[k]);
                s += (a.x + a.y) + (bb.x + bb.y);
            }
        } else {
            float2 a;
            a = __half22float2(h0[0]); s += a.x * c0.x + a.y * c0.y;
            a = __half22float2(h0[1]); s += a.x * c0.z + a.y * c0.w;
            a = __half22float2(h0[2]); s += a.x * c1.x + a.y * c1.y;
            a = __half22float2(h0[3]); s += a.x * c1.z + a.y * c1.w;
            a = __half22float2(h1[0]); s += a.x * c2.x + a.y * c2.y;
            a = __half22float2(h1[1]); s += a.x * c2.z + a.y * c2.w;
            a = __half22float2(h1[2]); s += a.x * c3.x + a.y * c3.y;
            a = __half22float2(h1[3]); s += a.x * c3.z + a.y * c3.w;
        }
        s = warpSum(s);
        if (lane == 0) {
            int idx = b * Sn + row0 + rr;
            if (fresh) {
                vout[idx] = 1.0f / fmaxf(s, 1e-8f);
            } else {
                float vo = vout[idx];
                vout[idx] = vo / fmaxf(vo * s, 1e-8f);
            }
        }
    }
}

// ---------------- persistent Sinkhorn: all 10 iterations, 20 grid barriers -------
// 128 CTAs (8 per batch) x 256 threads; each warp owns 8 rows (2 passes of 4).
// 20 barriers per launch = even # sense flips -> barrier state self-restores
// across graph replays. No smem, low regs -> guaranteed co-residency.
__global__ void __launch_bounds__(256) sinkhorn_k() {
    int cta = blockIdx.x;                 // 0..127
    int b = cta >> 3, sub = cta & 7;
    int wid = threadIdx.x >> 5, lane = threadIdx.x & 31;
    int row0 = sub * 64 + wid * 8;        // this warp: rows [row0, row0+8)
    int sense = 0;
    for (int it = 0; it < 10; ++it) {
        bool f = (it == 0);
        sink4(g_Kh, g_c, g_r, b, row0,     lane, f, f);   // row step
        sink4(g_Kh, g_c, g_r, b, row0 + 4, lane, f, f);
        gridBar(sense);
        sink4(g_KTh, g_r, g_c, b, row0,     lane, false, f);  // col step
        sink4(g_KTh, g_r, g_c, b, row0 + 4, lane, false, f);
        gridBar(sense);
    }
}

// ---------------- loss = sum_b sum_ij r_i c_j K'_ij W_ij (K' scale cancels) ------
// 1024 CTAs (16 batches x 64 row-tiles of 8 rows) — latency-bound, go wide.
__global__ void __launch_bounds__(256) losspart_k() {
    __shared__ float sh[32];
    int bx = blockIdx.x;
    int b = bx >> 6, i0 = (bx & 63) * 8;
    int t = threadIdx.x;
    const uint4* K4 = (const uint4*)g_Kh + (size_t)(b * Sn + i0) * (Sn / 8);
    const uint4* W4 = (const uint4*)g_Wh + (size_t)(b * Sn + i0) * (Sn / 8);
    float p = 0.0f;
#pragma unroll
    for (int m = 0; m < 2; m++) {
        int o = t + 256 * m;                    // 8 rows x 64 uint4 = 512
        int i = o >> 6, j8 = o & 63;
        uint4 ku = K4[o], wu = W4[o];
        const __half2* kh = (const __half2*)&ku;
        const __half2* wh = (const __half2*)&wu;
        const float4* cp = (const float4*)(g_c + b * Sn + j8 * 8);
        float4 c0 = cp[0], c1 = cp[1];
        float ri = g_r[b * Sn + i0 + i];
        float2 k0, w0;
        float s = 0.0f;
        k0 = __half22float2(kh[0]); w0 = __half22float2(wh[0]);
        s += c0.x * k0.x * w0.x + c0.y * k0.y * w0.y;
        k0 = __half22float2(kh[1]); w0 = __half22float2(wh[1]);
        s += c0.z * k0.x * w0.x + c0.w * k0.y * w0.y;
        k0 = __half22float2(kh[2]); w0 = __half22float2(wh[2]);
        s += c1.x * k0.x * w0.x + c1.y * k0.y * w0.y;
        k0 = __half22float2(kh[3]); w0 = __half22float2(wh[3]);
        s += c1.z * k0.x * w0.x + c1.w * k0.y * w0.y;
        p += ri * s;
    }
    p = blockSum(p, sh);
    if (t == 0) g_part[bx] = p;
}

__global__ void __launch_bounds__(256) lossfin_k(float* __restrict__ out) {
    __shared__ float sh[32];
    int t = threadIdx.x;
    float v = g_part[t] + g_part[t + 256] + g_part[t + 512] + g_part[t + 768];
    v = blockSum(v, sh);
    if (t == 0) out[0] = v * (0.001f / 16.0f);  // mean over B of 0.001 * loss_b
}

// ---------------- launch --------------------------------------------------------
extern "C" void kernel_launch(void* const* d_in, const int* in_sizes, int n_in,
                              void* d_out, int out_size) {
    const float* ys = (const float*)d_in[0];
    const float* yt = (const float*)d_in[1];
    (void)in_sizes; (void)n_in; (void)out_size;

    // idempotent; called every time (no static guards allowed)
    cudaFuncSetAttribute(minsum_k, cudaFuncAttributeMaxDynamicSharedMemorySize,
                         98304);

    softmax_k<<<2 * Bn * Sn, 256>>>(ys, yt);

    dim3 grid(Sn / 128, Sn / 128, Bn);          // 4 x 4 x 16 = 256 CTAs
    minsum_k<<<grid, 256, 98304>>>();

    sinkhorn_k<<<SINK_CTAS, 256>>>();           // all 10 iterations, 1 launch

    losspart_k<<<Bn * 64, 256>>>();             // 1024 CTAs
    lossfin_k<<<1, 256>>>((float*)d_out);
}

// round 17
// speedup vs baseline: 1.0396x; 1.0145x over previous
#include <cuda_runtime.h>
#include <cuda_fp16.h>
#include <math.h>

#define Bn 16
#define Sn 512
#define Vn 4096
#define CHUNKS (Vn / 128)          // 32 k-chunks of 128 bytes
#define SINK_CTAS 128              // persistent Sinkhorn grid (< 148 SMs)

// ---------------- scratch (device globals; no allocation allowed) ----------------
__device__ __align__(256) unsigned char g_qs[Bn * Sn * Vn];  // q8 softmax(y_s/T)
__device__ __align__(256) unsigned char g_qt[Bn * Sn * Vn];  // q8 softmax(y_t/T)
__device__ __align__(256) __half g_Wh[Bn * Sn * Sn];         // L1 cost, fp16
__device__ __align__(256) __half g_Kh[Bn * Sn * Sn];         // (exp(-10W)+1e-8)*8192
__device__ __align__(256) __half g_KTh[Bn * Sn * Sn];        // transpose of g_Kh
__device__ __align__(256) float g_r[Bn * Sn];                // Sinkhorn row scalings
__device__ __align__(256) float g_c[Bn * Sn];                // Sinkhorn col scalings
__device__ __align__(256) float g_part[SINK_CTAS];           // loss partials
__device__ int g_bcnt = 0;                                   // barrier arrive counter
__device__ volatile int g_bsense_v = 0;                      // barrier sense (even flips/launch)

// ---------------- cp.async helpers ----------------
__device__ __forceinline__ void cp16(unsigned dst, const void* src) {
    asm volatile("cp.async.ca.shared.global [%0], [%1], 16;" :: "r"(dst), "l"(src));
}
#define CP_COMMIT() asm volatile("cp.async.commit_group;")
#define CP_WAIT1()  asm volatile("cp.async.wait_group 1;")
#define CP_WAIT0()  asm volatile("cp.async.wait_group 0;")

// ---------------- reductions ----------------
__device__ __forceinline__ float warpSum(float v) {
#pragma unroll
    for (int o = 16; o; o >>= 1) v += __shfl_xor_sync(0xffffffffu, v, o);
    return v;
}
__device__ __forceinline__ float warpMax(float v) {
#pragma unroll
    for (int o = 16; o; o >>= 1) v = fmaxf(v, __shfl_xor_sync(0xffffffffu, v, o));
    return v;
}
__device__ __forceinline__ float blockSum(float v, float* sh) {
    int t = threadIdx.x;
    __syncthreads();
    v = warpSum(v);
    if ((t & 31) == 0) sh[t >> 5] = v;
    __syncthreads();
    float r = (t < (int)(blockDim.x >> 5)) ? sh[t] : 0.0f;
    if (t < 32) {
        r = warpSum(r);
        if (t == 0) sh[0] = r;
    }
    __syncthreads();
    return sh[0];
}
__device__ __forceinline__ float blockMax(float v, float* sh) {
    int t = threadIdx.x;
    __syncthreads();
    v = warpMax(v);
    if ((t & 31) == 0) sh[t >> 5] = v;
    __syncthreads();
    float r = (t < (int)(blockDim.x >> 5)) ? sh[t] : -INFINITY;
    if (t < 32) {
        r = warpMax(r);
        if (t == 0) sh[0] = r;
    }
    __syncthreads();
    return sh[0];
}

// ---------------- device-wide barrier: atomic arrive, VOLATILE-LOAD poll ---------
// Release is a fenced plain store; pollers issue non-serializing L2 reads.
// Even number of flips per launch -> g_bsense_v returns to 0 (graph-replay safe).
__device__ __forceinline__ void gridBar(int& sense) {
    __syncthreads();
    if (threadIdx.x == 0) {
        sense ^= 1;
        __threadfence();
        if (atomicAdd(&g_bcnt, 1) == SINK_CTAS - 1) {
            g_bcnt = 0;                      // all arrived; nobody touches until release
            __threadfence();
            g_bsense_v = sense;              // release
        } else {
            while (g_bsense_v != sense) { }  // volatile L2 poll (128 threads chip-wide)
        }
        __threadfence();                     // acquire
    }
    __syncthreads();
}

// ---------------- softmax over V (T=2) -> uint8 quantized (scale 2^17) -----------
__global__ void __launch_bounds__(256) softmax_k(const float* __restrict__ ys,
                                                 const float* __restrict__ yt) {
    __shared__ float sh[32];
    int row = blockIdx.x;                       // 0 .. 2*B*S-1
    const float4* src;
    uint4* dst;
    if (row < Bn * Sn) {
        src = (const float4*)ys + (size_t)row * (Vn / 4);
        dst = (uint4*)g_qs + (size_t)row * (Vn / 16);
    } else {
        int r2 = row - Bn * Sn;
        src = (const float4*)yt + (size_t)r2 * (Vn / 4);
        dst = (uint4*)g_qt + (size_t)r2 * (Vn / 16);
    }
    int t = threadIdx.x;                        // thread owns v in [16t, 16t+16)
    float4 x[4];
    float m = -INFINITY;
#pragma unroll
    for (int k = 0; k < 4; k++) {
        float4 v = src[4 * t + k];
        v.x *= 0.5f; v.y *= 0.5f; v.z *= 0.5f; v.w *= 0.5f;   // y / T, T = 2
        x[k] = v;
        m = fmaxf(m, fmaxf(fmaxf(v.x, v.y), fmaxf(v.z, v.w)));
    }
    m = blockMax(m, sh);
    float s = 0.0f;
#pragma unroll
    for (int k = 0; k < 4; k++) {
        x[k].x = __expf(x[k].x - m);
        x[k].y = __expf(x[k].y - m);
        x[k].z = __expf(x[k].z - m);
        x[k].w = __expf(x[k].w - m);
        s += (x[k].x + x[k].y) + (x[k].z + x[k].w);
    }
    s = blockSum(s, sh);
    float f = 131072.0f / s;                    // p * 2^17
    unsigned q[16];
#pragma unroll
    for (int k = 0; k < 4; k++) {
        q[4 * k + 0] = __float2uint_rn(fminf(x[k].x * f, 255.0f));
        q[4 * k + 1] = __float2uint_rn(fminf(x[k].y * f, 255.0f));
        q[4 * k + 2] = __float2uint_rn(fminf(x[k].z * f, 255.0f));
        q[4 * k + 3] = __float2uint_rn(fminf(x[k].w * f, 255.0f));
    }
    uint4 u;
    u.x = q[0]  | (q[1] << 8)  | (q[2] << 16)  | (q[3] << 24);
    u.y = q[4]  | (q[5] << 8)  | (q[6] << 16)  | (q[7] << 24);
    u.z = q[8]  | (q[9] << 8)  | (q[10] << 16) | (q[11] << 24);
    u.w = q[12] | (q[13] << 8) | (q[14] << 16) | (q[15] << 24);
    dst[t] = u;
}

// ---------------- L1 cdist via integer SAD; emits W, K', K'^T (all fp16) ----------
// CTA 128x128 tile, 256 threads (16x16), 8x8 outputs/thread.
// cp.async triple-buffered smem (3 stages x (A,B) x 16KB = 96KB), 1 sync/chunk.
// (256,1): full register budget — (256,2) forces acc spills (R14: +190us).
extern __shared__ uint4 smem_dyn[];
__global__ void __launch_bounds__(256, 1) minsum_k() {
    int b  = blockIdx.z;
    int i0 = blockIdx.x * 128;
    int j0 = blockIdx.y * 128;
    int tid = threadIdx.x;
    int tx = tid & 15, ty = tid >> 4;

    unsigned sbase = (unsigned)__cvta_generic_to_shared(smem_dyn);

    // loader: word w = tid&7, base row lr = tid>>3 (32 rows/pass, 4 passes)
    int w = tid & 7, lr = tid >> 3;
    const char* Ag = (const char*)g_qs + (size_t)(b * Sn + i0) * Vn;
    const char* Bg = (const char*)g_qt + (size_t)(b * Sn + j0) * Vn;

    auto issue = [&](int c, int st) {
        unsigned sa = sbase + (unsigned)(st * 2048) * 16;
        unsigned sb = sa + 1024 * 16;
        const char* ag = Ag + c * 128 + w * 16;
        const char* bg = Bg + c * 128 + w * 16;
#pragma unroll
        for (int m = 0; m < 4; m++) {
            int rr = lr + 32 * m;
            int col = w ^ ((rr ^ (rr >> 3)) & 7);
            unsigned so = (unsigned)(rr * 8 + col) * 16;
            cp16(sa + so, ag + (size_t)rr * Vn);
            cp16(sb + so, bg + (size_t)rr * Vn);
        }
        CP_COMMIT();
    };

    unsigned acc[8][8];
#pragma unroll
    for (int ii = 0; ii < 8; ii++)
#pragma unroll
        for (int jj = 0; jj < 8; jj++) acc[ii][jj] = 0u;

    issue(0, 0);
    issue(1, 1);

    for (int c = 0; c < CHUNKS; ++c) {
        if (c + 1 < CHUNKS) CP_WAIT1(); else CP_WAIT0();
        __syncthreads();                 // chunk c resident; all done reading c-1
        if (c + 2 < CHUNKS) issue(c + 2, (c + 2) % 3);

        const uint4* sa = smem_dyn + (c % 3) * 2048;
        const uint4* sb = sa + 1024;
#pragma unroll
        for (int gg = 0; gg < 8; ++gg) {        // 16 v per sub-chunk
            uint4 af[8], bf[8];
#pragma unroll
            for (int jj = 0; jj < 8; jj++)
                bf[jj] = sb[(8 * tx + jj) * 8 + (gg ^ ((jj ^ tx) & 7))];
#pragma unroll
            for (int ii = 0; ii < 8; ii++)
                af[ii] = sa[(8 * ty + ii) * 8 + (gg ^ ((ii ^ ty) & 7))];
#pragma unroll
            for (int ii = 0; ii < 8; ii++) {
#pragma unroll
                for (int jj = 0; jj < 8; jj++) {
                    acc[ii][jj] += __vsadu4(af[ii].x, bf[jj].x);
                    acc[ii][jj] += __vsadu4(af[ii].y, bf[jj].y);
                    acc[ii][jj] += __vsadu4(af[ii].z, bf[jj].z);
                    acc[ii][jj] += __vsadu4(af[ii].w, bf[jj].w);
                }
            }
        }
        __syncthreads();                 // done reading stage c%3 (reused at c+3)
    }

    // epilogue: W = acc/2^17; K' = (exp(-10*min(W,10)) + 1e-8) * 8192
    __half kt[8][8];                     // [jj][ii]
#pragma unroll
    for (int ii = 0; ii < 8; ii++) {
        int i = i0 + 8 * ty + ii;
        __align__(16) __half wv[8];
        __align__(16) __half kv[8];
#pragma unroll
        for (int jj = 0; jj < 8; jj++) {
            float W = (float)acc[ii][jj] * (1.0f / 131072.0f);
            float K = (__expf(-10.0f * fminf(W, 10.0f)) + 1e-8f) * 8192.0f;
            wv[jj] = __float2half_rn(W);
            kv[jj] = __float2half_rn(K);
            kt[jj][ii] = kv[jj];
        }
        size_t off = ((size_t)(b * Sn + i) * Sn + j0 + 8 * tx) >> 3;  // uint4 units
        ((uint4*)g_Wh)[off] = *(const uint4*)wv;
        ((uint4*)g_Kh)[off] = *(const uint4*)kv;
    }
#pragma unroll
    for (int jj = 0; jj < 8; jj++) {
        int j = j0 + 8 * tx + jj;
        size_t off = ((size_t)(b * Sn + j) * Sn + i0 + 8 * ty) >> 3;
        ((uint4*)g_KTh)[off] = *(const uint4*)kt[jj];
    }
}

// ---------------- one Sinkhorn half-step for 2 rows (warp-collective) ------------
__device__ __forceinline__ void sink2(const __half* __restrict__ M,
                                      const float* __restrict__ vin,
                                      float* __restrict__ vout,
                                      int b, int row0, int lane,
                                      bool ones, bool fresh) {
    float4 c0, c1, c2, c3;
    if (!ones) {
        const float4* vp = (const float4*)(vin + b * Sn) + lane * 4;
        c0 = vp[0]; c1 = vp[1]; c2 = vp[2]; c3 = vp[3];
    }
    const uint4* Mb = (const uint4*)(M + ((size_t)(b * Sn + row0)) * Sn) + lane * 2;
    uint4 u[4];
    u[0] = Mb[0];
    u[1] = Mb[1];
    u[2] = Mb[Sn / 8];
    u[3] = Mb[Sn / 8 + 1];
#pragma unroll
    for (int rr = 0; rr < 2; rr++) {
        const __half2* h0 = (const __half2*)&u[2 * rr];
        const __half2* h1 = (const __half2*)&u[2 * rr + 1];
        float s = 0.0f;
        if (ones) {
#pragma unroll
            for (int k = 0; k < 4; k++) {
                float2 a = __half22float2(h0[k]);
                float2 bb = __half22float2(h1[k]);
                s += (a.x + a.y) + (bb.x + bb.y);
            }
        } else {
            float2 a;
            a = __half22float2(h0[0]); s += a.x * c0.x + a.y * c0.y;
            a = __half22float2(h0[1]); s += a.x * c0.z + a.y * c0.w;
            a = __half22float2(h0[2]); s += a.x * c1.x + a.y * c1.y;
            a = __half22float2(h0[3]); s += a.x * c1.z + a.y * c1.w;
            a = __half22float2(h1[0]); s += a.x * c2.x + a.y * c2.y;
            a = __half22float2(h1[1]); s += a.x * c2.z + a.y * c2.w;
            a = __half22float2(h1[2]); s += a.x * c3.x + a.y * c3.y;
            a = __half22float2(h1[3]); s += a.x * c3.z + a.y * c3.w;
        }
        s = warpSum(s);
        if (lane == 0) {
            int idx = b * Sn + row0 + rr;
            if (fresh) {
                vout[idx] = 1.0f / fmaxf(s, 1e-8f);
            } else {
                float vo = vout[idx];
                vout[idx] = vo / fmaxf(vo * s, 1e-8f);
            }
        }
    }
}

// ---------------- persistent Sinkhorn + fused loss tail ---------------------------
// 128 CTAs x 1024 threads = 4096 warps; each warp owns 2 rows per phase (2x R13
// parallelism). 20 grid barriers (even -> sense self-restores for graph replay).
// After barrier 20: each CTA reduces its 64 rows of r_i c_j K_ij W_ij -> g_part.
__global__ void __launch_bounds__(1024) sinkhorn_k() {
    __shared__ float sh[32];
    int lane = threadIdx.x & 31;
    int gw = blockIdx.x * 32 + (threadIdx.x >> 5);   // global warp 0..4095
    int b = gw >> 8;                                  // 256 warps per batch
    int row0 = (gw & 255) * 2;                        // 2 rows per warp
    int sense = 0;
    for (int it = 0; it < 10; ++it) {
        bool f = (it == 0);
        sink2(g_Kh, g_c, g_r, b, row0, lane, f, f);       // row step
        gridBar(sense);
        sink2(g_KTh, g_r, g_c, b, row0, lane, false, f);  // col step
        gridBar(sense);
    }

    // ---- fused loss partials: CTA cta covers rows [sub*64, sub*64+64) of batch b2
    int cta = blockIdx.x;
    int b2 = cta >> 3, sub = cta & 7;
    int t = threadIdx.x;
    int row = sub * 64 + (t >> 4);                    // 64 rows x 16 thread-groups
    int j0 = (t & 15) * 32;                           // 32 cols per thread
    const uint4* K4 = (const uint4*)(g_Kh + ((size_t)(b2 * Sn + row)) * Sn + j0);
    const uint4* W4 = (const uint4*)(g_Wh + ((size_t)(b2 * Sn + row)) * Sn + j0);
    const float4* cp = (const float4*)(g_c + b2 * Sn + j0);
    float ri = g_r[b2 * Sn + row];
    float s = 0.0f;
#pragma unroll
    for (int m = 0; m < 4; m++) {                     // 4 x 8 halves = 32 cols
        uint4 ku = K4[m], wu = W4[m];
        const __half2* kh = (const __half2*)&ku;
        const __half2* wh = (const __half2*)&wu;
        float4 cv0 = cp[2 * m], cv1 = cp[2 * m + 1];
        float2 k0, w0;
        k0 = __half22float2(kh[0]); w0 = __half22float2(wh[0]);
        s += cv0.x * k0.x * w0.x + cv0.y * k0.y * w0.y;
        k0 = __half22float2(kh[1]); w0 = __half22float2(wh[1]);
        s += cv0.z * k0.x * w0.x + cv0.w * k0.y * w0.y;
        k0 = __half22float2(kh[2]); w0 = __half22float2(wh[2]);
        s += cv1.x * k0.x * w0.x + cv1.y * k0.y * w0.y;
        k0 = __half22float2(kh[3]); w0 = __half22float2(wh[3]);
        s += cv1.z * k0.x * w0.x + cv1.w * k0.y * w0.y;
    }
    float p = blockSum(ri * s, sh);
    if (t == 0) g_part[cta] = p;
}

__global__ void __launch_bounds__(256) lossfin_k(float* __restrict__ out) {
    __shared__ float sh[32];
    int t = threadIdx.x;
    float v = (t < SINK_CTAS) ? g_part[t] : 0.0f;
    v = blockSum(v, sh);
    if (t == 0) out[0] = v * (0.001f / 16.0f);  // mean over B of 0.001 * loss_b
}

// ---------------- launch --------------------------------------------------------
extern "C" void kernel_launch(void* const* d_in, const int* in_sizes, int n_in,
                              void* d_out, int out_size) {
    const float* ys = (const float*)d_in[0];
    const float* yt = (const float*)d_in[1];
    (void)in_sizes; (void)n_in; (void)out_size;

    // idempotent; called every time (no static guards allowed)
    cudaFuncSetAttribute(minsum_k, cudaFuncAttributeMaxDynamicSharedMemorySize,
                         98304);

    softmax_k<<<2 * Bn * Sn, 256>>>(ys, yt);

    dim3 grid(Sn / 128, Sn / 128, Bn);          // 4 x 4 x 16 = 256 CTAs
    minsum_k<<<grid, 256, 98304>>>();

    sinkhorn_k<<<SINK_CTAS, 1024>>>();          // 10 iterations + loss partials

    lossfin_k<<<1, 256>>>((float*)d_out);
}